// round 15
// baseline (speedup 1.0000x reference)
#include <cuda_runtime.h>
#include <math.h>
#include <stdint.h>

#define B_     8
#define S_     1024
#define VOCAB_ 32000
#define EMBED_ 256
#define HID_   512
#define NTOK   (B_ * S_)

// ---------------- scratch (static device arrays; no allocation) ----------------
__device__ float g_X  [NTOK * EMBED_];
__device__ float g_xr [NTOK * HID_];
__device__ float g_xz [NTOK * HID_];
__device__ float g_xc [NTOK * HID_];
__device__ float g_hs [NTOK * HID_];     // tf32-rounded hidden states
__device__ float g_WoT[VOCAB_ * HID_];   // Wo transposed [N,K], tf32-rounded

// ---------------- helpers ----------------
__device__ __forceinline__ uint32_t s2u(const void* p) {
    return (uint32_t)__cvta_generic_to_shared(p);
}
__device__ __forceinline__ float tf32_rna(float x) {
    uint32_t u;
    asm("cvt.rna.tf32.f32 %0, %1;" : "=r"(u) : "f"(x));
    return __uint_as_float(u);
}
__device__ __forceinline__ void cluster_sync_() {
    asm volatile("barrier.cluster.arrive.aligned;" ::: "memory");
    asm volatile("barrier.cluster.wait.aligned;"   ::: "memory");
}
__device__ __forceinline__ void dsm_store(uint32_t saddr, int rank, float v) {
    uint32_t ra;
    asm volatile("mapa.shared::cluster.u32 %0, %1, %2;" : "=r"(ra) : "r"(saddr), "r"(rank));
    asm volatile("st.shared::cluster.f32 [%0], %1;" :: "r"(ra), "f"(v) : "memory");
}
__device__ __forceinline__ void cp16(uint32_t saddr, const void* g) {
    asm volatile("cp.async.cg.shared.global [%0], [%1], 16;"
                 :: "r"(saddr), "l"(g) : "memory");
}

// ---------------- 1) embedding gather ----------------
__global__ void gather_kernel(const int* __restrict__ tok,
                              const float* __restrict__ embed) {
    int t = blockIdx.x;
    int e = threadIdx.x << 2;
    int v = __ldg(tok + t);
    float4 val = *(const float4*)(embed + (size_t)v * EMBED_ + e);
    *(float4*)(g_X + (size_t)t * EMBED_ + e) = val;
}

// ---------------- 1b) Wo transpose + tf32 round: g_WoT[n][k] = rna(Wo[k][n]) ----------------
__global__ void transpose_wo(const float* __restrict__ Wo) {
    __shared__ float tile[32][33];
    int n0 = blockIdx.x * 32, k0 = blockIdx.y * 32;
    int tx = threadIdx.x, ty = threadIdx.y;   // 32 x 8
#pragma unroll
    for (int i = 0; i < 4; i++)
        tile[ty + i * 8][tx] = Wo[(size_t)(k0 + ty + i * 8) * VOCAB_ + n0 + tx];
    __syncthreads();
#pragma unroll
    for (int i = 0; i < 4; i++)
        g_WoT[(size_t)(n0 + ty + i * 8) * HID_ + k0 + tx] = tf32_rna(tile[tx][ty + i * 8]);
}

// ---------------- 2) fp32 tiled GEMM: all 3 x-projections in one launch ----------------
__global__ void __launch_bounds__(256, 2) gemm_f32x3(
    const float* __restrict__ A,
    const float* __restrict__ W0, const float* __restrict__ W1, const float* __restrict__ W2,
    const float* __restrict__ b0, const float* __restrict__ b1, const float* __restrict__ b2,
    float* __restrict__ C0, float* __restrict__ C1, float* __restrict__ C2)
{
    const int BM = 128, BN = 128, BK = 32;
    const int N = HID_, K = EMBED_;
    __shared__ float As[BK][BM + 4];
    __shared__ float Bs[BK][BN];

    const float* Bg  = (blockIdx.z == 0) ? W0 : (blockIdx.z == 1) ? W1 : W2;
    const float* bia = (blockIdx.z == 0) ? b0 : (blockIdx.z == 1) ? b1 : b2;
    float*       C   = (blockIdx.z == 0) ? C0 : (blockIdx.z == 1) ? C1 : C2;

    int tid = threadIdx.x;
    int bm = blockIdx.y * BM;
    int bn = blockIdx.x * BN;
    int tx = tid & 15;
    int ty = tid >> 4;

    float acc[8][8];
#pragma unroll
    for (int i = 0; i < 8; i++)
#pragma unroll
        for (int j = 0; j < 8; j++) acc[i][j] = 0.f;

    int arow = tid >> 3;
    int acol = (tid & 7) << 2;
    int brow = tid >> 5;
    int bcol = (tid & 31) << 2;

    for (int k0 = 0; k0 < K; k0 += BK) {
#pragma unroll
        for (int p = 0; p < 4; p++) {
            int r = arow + p * 32;
            float4 v = *(const float4*)(A + (size_t)(bm + r) * K + k0 + acol);
            As[acol + 0][r] = v.x; As[acol + 1][r] = v.y;
            As[acol + 2][r] = v.z; As[acol + 3][r] = v.w;
        }
#pragma unroll
        for (int p = 0; p < 4; p++) {
            int r = brow + p * 8;
            *(float4*)(&Bs[r][bcol]) =
                *(const float4*)(Bg + (size_t)(k0 + r) * N + bn + bcol);
        }
        __syncthreads();

#pragma unroll
        for (int kk = 0; kk < BK; kk++) {
            float a[8], b[8];
            *(float4*)(a)     = *(const float4*)(&As[kk][ty * 4]);
            *(float4*)(a + 4) = *(const float4*)(&As[kk][64 + ty * 4]);
            *(float4*)(b)     = *(const float4*)(&Bs[kk][tx * 4]);
            *(float4*)(b + 4) = *(const float4*)(&Bs[kk][64 + tx * 4]);
#pragma unroll
            for (int i = 0; i < 8; i++)
#pragma unroll
                for (int j = 0; j < 8; j++)
                    acc[i][j] = fmaf(a[i], b[j], acc[i][j]);
        }
        __syncthreads();
    }

    float4 bv0 = *(const float4*)(bia + bn + tx * 4);
    float4 bv1 = *(const float4*)(bia + bn + 64 + tx * 4);
#pragma unroll
    for (int i = 0; i < 8; i++) {
        int row = bm + ((i < 4) ? (ty * 4 + i) : (64 + ty * 4 + (i - 4)));
        float4 o0, o1;
        o0.x = acc[i][0] + bv0.x; o0.y = acc[i][1] + bv0.y;
        o0.z = acc[i][2] + bv0.z; o0.w = acc[i][3] + bv0.w;
        o1.x = acc[i][4] + bv1.x; o1.y = acc[i][5] + bv1.y;
        o1.z = acc[i][6] + bv1.z; o1.w = acc[i][7] + bv1.w;
        *(float4*)(C + (size_t)row * N + bn + tx * 4)      = o0;
        *(float4*)(C + (size_t)row * N + bn + 64 + tx * 4) = o1;
    }
}

// ---------------- 3) GRU recurrence (proven R8 config: 8-CTA cluster, KC1=20) ----
#define KC1 20

__global__ void __launch_bounds__(512, 1) __cluster_dims__(8, 1, 1)
gru_kernel(const float* __restrict__ Wr, const float* __restrict__ Wz,
           const float* __restrict__ Wc)
{
    __shared__ float  h_s [HID_];
    __shared__ float  rh_s[HID_];
    __shared__ float  z_s [64];
    __shared__ float4 part[512];

    int tid   = threadIdx.x;
    int batch = blockIdx.x >> 3;
    int jbase = (blockIdx.x & 7) << 6;

    uint32_t rh_base = s2u(rh_s);
    uint32_t h_base  = s2u(h_s);

    h_s[tid] = 0.f;
    __syncthreads();
    cluster_sync_();

    int g1  = tid >> 8;
    int jq1 = tid & 15;
    int kp1 = (tid >> 4) & 15;
    const float* W1 = g1 ? Wz : Wr;
    const float4* w1base =
        (const float4*)(W1 + (size_t)(kp1 * 32) * HID_ + jbase + jq1 * 4);

    int jq2 = tid & 15;
    int kp2 = tid >> 4;
    const float4* w2base =
        (const float4*)(Wc + (size_t)(kp2 * 16) * HID_ + jbase + jq2 * 4);

    float4 wc[KC1];
#pragma unroll
    for (int i = 0; i < KC1; i++) wc[i] = __ldg(w1base + i * (HID_ / 4));
    const float4* w1rest = w1base + KC1 * (HID_ / 4);

    for (int t = 0; t < S_; t++) {
        int row = (batch << 10) + t;

        float xpre1 = 0.f;
        if (tid < 128) {
            int g2 = tid >> 6, jl = tid & 63;
            const float* xg = g2 ? g_xz : g_xr;
            xpre1 = __ldg(xg + (size_t)row * HID_ + jbase + jl);
        }

        // ---- phase 1: r and z pre-activations (h @ W_h) ----
        {
            float4 acc = make_float4(0.f, 0.f, 0.f, 0.f);
            int kb = kp1 * 32;
#pragma unroll
            for (int i = 0; i < KC1; i++) {
                float hv = h_s[kb + i];
                acc.x = fmaf(hv, wc[i].x, acc.x); acc.y = fmaf(hv, wc[i].y, acc.y);
                acc.z = fmaf(hv, wc[i].z, acc.z); acc.w = fmaf(hv, wc[i].w, acc.w);
            }
            const float4* wp = w1rest;
#pragma unroll
            for (int i = KC1; i < 32; i++) {
                float hv = h_s[kb + i];
                float4 w = __ldg(wp);
                acc.x = fmaf(hv, w.x, acc.x); acc.y = fmaf(hv, w.y, acc.y);
                acc.z = fmaf(hv, w.z, acc.z); acc.w = fmaf(hv, w.w, acc.w);
                wp += HID_ / 4;
            }
            part[(g1 << 8) + (kp1 << 4) + jq1] = acc;
        }
        __syncthreads();

        if (tid < 128) {
            int g2 = tid >> 6, jl = tid & 63;
            int jq = jl >> 2, comp = jl & 3;
            float sum = xpre1;
            const float* pf = (const float*)part + (g2 << 10) + (jq << 2) + comp;
#pragma unroll
            for (int kp = 0; kp < 16; kp++) sum += pf[kp * 64];
            float s = 1.f / (1.f + expf(-sum));
            if (g2 == 0) {
                float rh = s * h_s[jbase + jl];
                uint32_t addr = rh_base + (uint32_t)(jbase + jl) * 4u;
#pragma unroll
                for (int rk = 0; rk < 8; rk++) dsm_store(addr, rk, rh);
            } else {
                z_s[jl] = s;
            }
        }
        cluster_sync_();

        float xpre2 = 0.f;
        if (tid < 64)
            xpre2 = __ldg(g_xc + (size_t)row * HID_ + jbase + tid);

        // ---- phase 2: candidate c, h update ----
        {
            float4 acc = make_float4(0.f, 0.f, 0.f, 0.f);
            const float4* wp = w2base;
            int kb = kp2 * 16;
#pragma unroll 8
            for (int i = 0; i < 16; i++) {
                float rv = rh_s[kb + i];
                float4 w = __ldg(wp);
                acc.x = fmaf(rv, w.x, acc.x); acc.y = fmaf(rv, w.y, acc.y);
                acc.z = fmaf(rv, w.z, acc.z); acc.w = fmaf(rv, w.w, acc.w);
                wp += HID_ / 4;
            }
            part[(kp2 << 4) + jq2] = acc;
        }
        __syncthreads();

        if (tid < 64) {
            int jq = tid >> 2, comp = tid & 3;
            float sum = xpre2;
            const float* pf = (const float*)part + (jq << 2) + comp;
#pragma unroll
            for (int kp = 0; kp < 32; kp++) sum += pf[kp * 64];
            float c    = tanhf(sum);
            float z    = z_s[tid];
            float hold = h_s[jbase + tid];
            float hn   = (1.f - z) * c + z * hold;
            g_hs[(size_t)row * HID_ + jbase + tid] = tf32_rna(hn);
            uint32_t addr = h_base + (uint32_t)(jbase + tid) * 4u;
#pragma unroll
            for (int rk = 0; rk < 8; rk++) dsm_store(addr, rk, hn);
        }
        cluster_sync_();
    }
}

// ---------------- 4) output projection: mma.sync tf32, 256x128 tile, 512 thr ----
// C[8192,32000] = hs @ WoT^T + bo. CTA tile 256x128, K-chunk 32, 16 warps (4x4),
// warp tile 64x32. 3-stage cp.async ring, one __syncthreads per chunk.
// Traffic: 6.1 GB total (vs 8.2 GB at 128x128).
#define ROWP    36
#define ATILEF  (256 * ROWP)              // 9216 floats
#define BTILEF  (128 * ROWP)              // 4608 floats
#define BUFF    (ATILEF + BTILEF)         // 13824 floats = 55296 B per stage
#define NSTAGE  3
#define PROJ_SMEM (NSTAGE * BUFF * 4)     // 165888 bytes (1 CTA/SM)

__global__ void __launch_bounds__(512, 1) gemm_mma(
    const float* __restrict__ A,   // g_hs  [8192,512], tf32 values
    const float* __restrict__ BT,  // g_WoT [32000,512], tf32 values
    const float* __restrict__ bias,
    float* __restrict__ C)
{
    extern __shared__ float sm[];
    uint32_t sbase = s2u(sm);
    int tid = threadIdx.x, lane = tid & 31, wid = tid >> 5;
    int wm = (wid >> 2) << 6;             // 0 / 64 / 128 / 192
    int wn = (wid & 3) << 5;              // 0 / 32 / 64 / 96
    size_t bm = (size_t)blockIdx.x * 256;
    size_t bn = (size_t)blockIdx.y * 128;

    float acc[4][4][4];
#pragma unroll
    for (int i = 0; i < 4; i++)
#pragma unroll
        for (int j = 0; j < 4; j++)
#pragma unroll
            for (int r = 0; r < 4; r++) acc[i][j][r] = 0.f;

    // async-copy one K-chunk (A: 256x32, B: 128x32) into stage s
    auto ISSUE = [&](int ch, int s) {
        uint32_t sa = sbase + (uint32_t)(s * BUFF) * 4u;
        uint32_t sb = sa + (uint32_t)ATILEF * 4u;
#pragma unroll
        for (int p = 0; p < 6; p++) {
            int idx = tid + (p << 9);      // 0..3071
            if (idx < 2048) {              // A: 2048 16B-granules
                int row = idx >> 3, q = idx & 7;
                uint32_t so = (uint32_t)(row * ROWP + q * 4) * 4u;
                cp16(sa + so, A + (bm + row) * HID_ + ch * 32 + q * 4);
            } else {                       // B: 1024 granules
                int idx2 = idx - 2048;
                int row = idx2 >> 3, q = idx2 & 7;
                uint32_t so = (uint32_t)(row * ROWP + q * 4) * 4u;
                cp16(sb + so, BT + (bn + row) * HID_ + ch * 32 + q * 4);
            }
        }
        asm volatile("cp.async.commit_group;" ::: "memory");
    };

    int r4 = lane >> 2, c4 = lane & 3;

    auto COMPUTE = [&](int s) {
        const float* pA = sm + s * BUFF;
        const float* pB = pA + ATILEF;
#pragma unroll
        for (int ks = 0; ks < 4; ks++) {
            uint32_t af[4][4];
            uint32_t bf[4][2];
#pragma unroll
            for (int i = 0; i < 4; i++) {
                const float* base = pA + (wm + i * 16 + r4) * ROWP + ks * 8 + c4;
                af[i][0] = __float_as_uint(base[0]);
                af[i][1] = __float_as_uint(base[8 * ROWP]);
                af[i][2] = __float_as_uint(base[4]);
                af[i][3] = __float_as_uint(base[8 * ROWP + 4]);
            }
#pragma unroll
            for (int j = 0; j < 4; j++) {
                const float* base = pB + (wn + j * 8 + r4) * ROWP + ks * 8 + c4;
                bf[j][0] = __float_as_uint(base[0]);
                bf[j][1] = __float_as_uint(base[4]);
            }
#pragma unroll
            for (int i = 0; i < 4; i++)
#pragma unroll
                for (int j = 0; j < 4; j++)
                    asm volatile(
                        "mma.sync.aligned.m16n8k8.row.col.f32.tf32.tf32.f32 "
                        "{%0,%1,%2,%3}, {%4,%5,%6,%7}, {%8,%9}, {%0,%1,%2,%3};"
                        : "+f"(acc[i][j][0]), "+f"(acc[i][j][1]),
                          "+f"(acc[i][j][2]), "+f"(acc[i][j][3])
                        : "r"(af[i][0]), "r"(af[i][1]), "r"(af[i][2]), "r"(af[i][3]),
                          "r"(bf[j][0]), "r"(bf[j][1]));
        }
    };

    ISSUE(0, 0);
    ISSUE(1, 1);
    int cs = 0;                            // compute stage (ch % 3)
    int is = 2;                            // issue stage for ch+2
#pragma unroll 1
    for (int ch = 0; ch < 16; ch++) {
        if (ch < 15) asm volatile("cp.async.wait_group 1;" ::: "memory");
        else         asm volatile("cp.async.wait_group 0;" ::: "memory");
        __syncthreads();                   // chunk ch visible; stage of ch-1 free
        if (ch + 2 < 16) {
            ISSUE(ch + 2, is);
            if (++is == NSTAGE) is = 0;
        }
        COMPUTE(cs);
        if (++cs == NSTAGE) cs = 0;
    }

    // epilogue
    float2 bv[4];
#pragma unroll
    for (int j = 0; j < 4; j++)
        bv[j] = __ldg((const float2*)(bias + bn + wn + (j << 3) + (c4 << 1)));

#pragma unroll
    for (int i = 0; i < 4; i++) {
        size_t row0 = bm + wm + (i << 4) + r4;
#pragma unroll
        for (int j = 0; j < 4; j++) {
            size_t col = bn + wn + (j << 3) + (c4 << 1);
            float2 v0 = make_float2(acc[i][j][0] + bv[j].x, acc[i][j][1] + bv[j].y);
            float2 v1 = make_float2(acc[i][j][2] + bv[j].x, acc[i][j][3] + bv[j].y);
            *(float2*)(C + row0 * VOCAB_ + col)       = v0;
            *(float2*)(C + (row0 + 8) * VOCAB_ + col) = v1;
        }
    }
}

// ---------------- launcher ----------------
extern "C" void kernel_launch(void* const* d_in, const int* in_sizes, int n_in,
                              void* d_out, int out_size) {
    const int*   tok   = (const int*)  d_in[0];
    const float* embed = (const float*)d_in[1];
    const float* Wr    = (const float*)d_in[2];
    const float* br    = (const float*)d_in[3];
    const float* Wz    = (const float*)d_in[4];
    const float* bz    = (const float*)d_in[5];
    const float* Wc    = (const float*)d_in[6];
    const float* bc    = (const float*)d_in[7];
    const float* Wo    = (const float*)d_in[8];
    const float* bo    = (const float*)d_in[9];
    float* out = (float*)d_out;

    float *xp, *xrp, *xzp, *xcp, *hsp, *wtp;
    cudaGetSymbolAddress((void**)&xp,  g_X);
    cudaGetSymbolAddress((void**)&xrp, g_xr);
    cudaGetSymbolAddress((void**)&xzp, g_xz);
    cudaGetSymbolAddress((void**)&xcp, g_xc);
    cudaGetSymbolAddress((void**)&hsp, g_hs);
    cudaGetSymbolAddress((void**)&wtp, g_WoT);

    cudaFuncSetAttribute(gemm_mma, cudaFuncAttributeMaxDynamicSharedMemorySize,
                         PROJ_SMEM);

    cudaStream_t s2;
    cudaStreamCreate(&s2);
    cudaEvent_t evRoot, evT;
    cudaEventCreateWithFlags(&evRoot, cudaEventDisableTiming);
    cudaEventCreateWithFlags(&evT,    cudaEventDisableTiming);

    // fork FROM the capture stream (R13 lesson: side stream must first wait on
    // an event recorded on stream 0 to join the capture graph).
    cudaEventRecord(evRoot, 0);
    cudaStreamWaitEvent(s2, evRoot, 0);
    transpose_wo<<<dim3(VOCAB_ / 32, HID_ / 32), dim3(32, 8), 0, s2>>>(Wo);
    cudaEventRecord(evT, s2);

    // main stream: gather -> x-projections -> GRU
    gather_kernel<<<NTOK, 64>>>(tok, embed);
    gemm_f32x3<<<dim3(HID_ / 128, NTOK / 128, 3), 256>>>(
        xp,
        Wr + (size_t)HID_ * HID_, Wz + (size_t)HID_ * HID_, Wc + (size_t)HID_ * HID_,
        br, bz, bc, xrp, xzp, xcp);
    gru_kernel<<<64, 512>>>(Wr, Wz, Wc);

    // join transpose before the projection consumes g_WoT
    cudaStreamWaitEvent(0, evT, 0);
    gemm_mma<<<dim3(NTOK / 256, VOCAB_ / 128), 512, PROJ_SMEM>>>(hsp, wtp, bo, out);

    cudaEventDestroy(evRoot);
    cudaEventDestroy(evT);
    cudaStreamDestroy(s2);
}

// round 16
// speedup vs baseline: 1.0074x; 1.0074x over previous
#include <cuda_runtime.h>
#include <math.h>
#include <stdint.h>

#define B_     8
#define S_     1024
#define VOCAB_ 32000
#define EMBED_ 256
#define HID_   512
#define NTOK   (B_ * S_)

// ---------------- scratch (static device arrays; no allocation) ----------------
__device__ float g_xr [NTOK * HID_];
__device__ float g_xz [NTOK * HID_];
__device__ float g_xc [NTOK * HID_];
__device__ float g_hs [NTOK * HID_];     // tf32-rounded hidden states
__device__ float g_WoT[VOCAB_ * HID_];   // Wo transposed [N,K], tf32-rounded

// ---------------- helpers ----------------
__device__ __forceinline__ uint32_t s2u(const void* p) {
    return (uint32_t)__cvta_generic_to_shared(p);
}
__device__ __forceinline__ float tf32_rna(float x) {
    uint32_t u;
    asm("cvt.rna.tf32.f32 %0, %1;" : "=r"(u) : "f"(x));
    return __uint_as_float(u);
}
__device__ __forceinline__ void cluster_sync_() {
    asm volatile("barrier.cluster.arrive.aligned;" ::: "memory");
    asm volatile("barrier.cluster.wait.aligned;"   ::: "memory");
}
__device__ __forceinline__ void dsm_store(uint32_t saddr, int rank, float v) {
    uint32_t ra;
    asm volatile("mapa.shared::cluster.u32 %0, %1, %2;" : "=r"(ra) : "r"(saddr), "r"(rank));
    asm volatile("st.shared::cluster.f32 [%0], %1;" :: "r"(ra), "f"(v) : "memory");
}
__device__ __forceinline__ void cp16(uint32_t saddr, const void* g) {
    asm volatile("cp.async.cg.shared.global [%0], [%1], 16;"
                 :: "r"(saddr), "l"(g) : "memory");
}

// ---------------- 1) Wo transpose + tf32 round: g_WoT[n][k] = rna(Wo[k][n]) ----------------
__global__ void transpose_wo(const float* __restrict__ Wo) {
    __shared__ float tile[32][33];
    int n0 = blockIdx.x * 32, k0 = blockIdx.y * 32;
    int tx = threadIdx.x, ty = threadIdx.y;   // 32 x 8
#pragma unroll
    for (int i = 0; i < 4; i++)
        tile[ty + i * 8][tx] = Wo[(size_t)(k0 + ty + i * 8) * VOCAB_ + n0 + tx];
    __syncthreads();
#pragma unroll
    for (int i = 0; i < 4; i++)
        g_WoT[(size_t)(n0 + ty + i * 8) * HID_ + k0 + tx] = tf32_rna(tile[tx][ty + i * 8]);
}

// ---------------- 2) fused gather + fp32 GEMM: all 3 x-projections ----------------
// A rows are gathered on the fly: A[row] = embed[tok[row]] (no g_X materialization).
// grid = (HID_/128, NTOK/128, 3); blockIdx.z selects gate (r,z,c).
__global__ void __launch_bounds__(256, 2) gemm_f32x3(
    const int* __restrict__ tok, const float* __restrict__ embed,
    const float* __restrict__ W0, const float* __restrict__ W1, const float* __restrict__ W2,
    const float* __restrict__ b0, const float* __restrict__ b1, const float* __restrict__ b2,
    float* __restrict__ C0, float* __restrict__ C1, float* __restrict__ C2)
{
    const int BM = 128, BN = 128, BK = 32;
    const int N = HID_, K = EMBED_;
    __shared__ float As[BK][BM + 4];
    __shared__ float Bs[BK][BN];
    __shared__ int   stok[BM];

    const float* Bg  = (blockIdx.z == 0) ? W0 : (blockIdx.z == 1) ? W1 : W2;
    const float* bia = (blockIdx.z == 0) ? b0 : (blockIdx.z == 1) ? b1 : b2;
    float*       C   = (blockIdx.z == 0) ? C0 : (blockIdx.z == 1) ? C1 : C2;

    int tid = threadIdx.x;
    int bm = blockIdx.y * BM;
    int bn = blockIdx.x * BN;
    int tx = tid & 15;
    int ty = tid >> 4;

    if (tid < BM) stok[tid] = __ldg(tok + bm + tid);
    __syncthreads();

    float acc[8][8];
#pragma unroll
    for (int i = 0; i < 8; i++)
#pragma unroll
        for (int j = 0; j < 8; j++) acc[i][j] = 0.f;

    int arow = tid >> 3;
    int acol = (tid & 7) << 2;
    int brow = tid >> 5;
    int bcol = (tid & 31) << 2;

    for (int k0 = 0; k0 < K; k0 += BK) {
#pragma unroll
        for (int p = 0; p < 4; p++) {
            int r = arow + p * 32;
            float4 v = *(const float4*)(embed + (size_t)stok[r] * K + k0 + acol);
            As[acol + 0][r] = v.x; As[acol + 1][r] = v.y;
            As[acol + 2][r] = v.z; As[acol + 3][r] = v.w;
        }
#pragma unroll
        for (int p = 0; p < 4; p++) {
            int r = brow + p * 8;
            *(float4*)(&Bs[r][bcol]) =
                *(const float4*)(Bg + (size_t)(k0 + r) * N + bn + bcol);
        }
        __syncthreads();

#pragma unroll
        for (int kk = 0; kk < BK; kk++) {
            float a[8], b[8];
            *(float4*)(a)     = *(const float4*)(&As[kk][ty * 4]);
            *(float4*)(a + 4) = *(const float4*)(&As[kk][64 + ty * 4]);
            *(float4*)(b)     = *(const float4*)(&Bs[kk][tx * 4]);
            *(float4*)(b + 4) = *(const float4*)(&Bs[kk][64 + tx * 4]);
#pragma unroll
            for (int i = 0; i < 8; i++)
#pragma unroll
                for (int j = 0; j < 8; j++)
                    acc[i][j] = fmaf(a[i], b[j], acc[i][j]);
        }
        __syncthreads();
    }

    float4 bv0 = *(const float4*)(bia + bn + tx * 4);
    float4 bv1 = *(const float4*)(bia + bn + 64 + tx * 4);
#pragma unroll
    for (int i = 0; i < 8; i++) {
        int row = bm + ((i < 4) ? (ty * 4 + i) : (64 + ty * 4 + (i - 4)));
        float4 o0, o1;
        o0.x = acc[i][0] + bv0.x; o0.y = acc[i][1] + bv0.y;
        o0.z = acc[i][2] + bv0.z; o0.w = acc[i][3] + bv0.w;
        o1.x = acc[i][4] + bv1.x; o1.y = acc[i][5] + bv1.y;
        o1.z = acc[i][6] + bv1.z; o1.w = acc[i][7] + bv1.w;
        *(float4*)(C + (size_t)row * N + bn + tx * 4)      = o0;
        *(float4*)(C + (size_t)row * N + bn + 64 + tx * 4) = o1;
    }
}

// ---------------- 3) GRU recurrence (proven R8 config: 8-CTA cluster, KC1=20) ----
#define KC1 20

__global__ void __launch_bounds__(512, 1) __cluster_dims__(8, 1, 1)
gru_kernel(const float* __restrict__ Wr, const float* __restrict__ Wz,
           const float* __restrict__ Wc)
{
    __shared__ float  h_s [HID_];
    __shared__ float  rh_s[HID_];
    __shared__ float  z_s [64];
    __shared__ float4 part[512];

    int tid   = threadIdx.x;
    int batch = blockIdx.x >> 3;
    int jbase = (blockIdx.x & 7) << 6;

    uint32_t rh_base = s2u(rh_s);
    uint32_t h_base  = s2u(h_s);

    h_s[tid] = 0.f;
    __syncthreads();
    cluster_sync_();

    int g1  = tid >> 8;
    int jq1 = tid & 15;
    int kp1 = (tid >> 4) & 15;
    const float* W1 = g1 ? Wz : Wr;
    const float4* w1base =
        (const float4*)(W1 + (size_t)(kp1 * 32) * HID_ + jbase + jq1 * 4);

    int jq2 = tid & 15;
    int kp2 = tid >> 4;
    const float4* w2base =
        (const float4*)(Wc + (size_t)(kp2 * 16) * HID_ + jbase + jq2 * 4);

    float4 wc[KC1];
#pragma unroll
    for (int i = 0; i < KC1; i++) wc[i] = __ldg(w1base + i * (HID_ / 4));
    const float4* w1rest = w1base + KC1 * (HID_ / 4);

    for (int t = 0; t < S_; t++) {
        int row = (batch << 10) + t;

        float xpre1 = 0.f;
        if (tid < 128) {
            int g2 = tid >> 6, jl = tid & 63;
            const float* xg = g2 ? g_xz : g_xr;
            xpre1 = __ldg(xg + (size_t)row * HID_ + jbase + jl);
        }

        // ---- phase 1: r and z pre-activations (h @ W_h) ----
        {
            float4 acc = make_float4(0.f, 0.f, 0.f, 0.f);
            int kb = kp1 * 32;
#pragma unroll
            for (int i = 0; i < KC1; i++) {
                float hv = h_s[kb + i];
                acc.x = fmaf(hv, wc[i].x, acc.x); acc.y = fmaf(hv, wc[i].y, acc.y);
                acc.z = fmaf(hv, wc[i].z, acc.z); acc.w = fmaf(hv, wc[i].w, acc.w);
            }
            const float4* wp = w1rest;
#pragma unroll
            for (int i = KC1; i < 32; i++) {
                float hv = h_s[kb + i];
                float4 w = __ldg(wp);
                acc.x = fmaf(hv, w.x, acc.x); acc.y = fmaf(hv, w.y, acc.y);
                acc.z = fmaf(hv, w.z, acc.z); acc.w = fmaf(hv, w.w, acc.w);
                wp += HID_ / 4;
            }
            part[(g1 << 8) + (kp1 << 4) + jq1] = acc;
        }
        __syncthreads();

        if (tid < 128) {
            int g2 = tid >> 6, jl = tid & 63;
            int jq = jl >> 2, comp = jl & 3;
            float sum = xpre1;
            const float* pf = (const float*)part + (g2 << 10) + (jq << 2) + comp;
#pragma unroll
            for (int kp = 0; kp < 16; kp++) sum += pf[kp * 64];
            float s = 1.f / (1.f + expf(-sum));
            if (g2 == 0) {
                float rh = s * h_s[jbase + jl];
                uint32_t addr = rh_base + (uint32_t)(jbase + jl) * 4u;
#pragma unroll
                for (int rk = 0; rk < 8; rk++) dsm_store(addr, rk, rh);
            } else {
                z_s[jl] = s;
            }
        }
        cluster_sync_();

        float xpre2 = 0.f;
        if (tid < 64)
            xpre2 = __ldg(g_xc + (size_t)row * HID_ + jbase + tid);

        // ---- phase 2: candidate c, h update ----
        {
            float4 acc = make_float4(0.f, 0.f, 0.f, 0.f);
            const float4* wp = w2base;
            int kb = kp2 * 16;
#pragma unroll 8
            for (int i = 0; i < 16; i++) {
                float rv = rh_s[kb + i];
                float4 w = __ldg(wp);
                acc.x = fmaf(rv, w.x, acc.x); acc.y = fmaf(rv, w.y, acc.y);
                acc.z = fmaf(rv, w.z, acc.z); acc.w = fmaf(rv, w.w, acc.w);
                wp += HID_ / 4;
            }
            part[(kp2 << 4) + jq2] = acc;
        }
        __syncthreads();

        if (tid < 64) {
            int jq = tid >> 2, comp = tid & 3;
            float sum = xpre2;
            const float* pf = (const float*)part + (jq << 2) + comp;
#pragma unroll
            for (int kp = 0; kp < 32; kp++) sum += pf[kp * 64];
            float c    = tanhf(sum);
            float z    = z_s[tid];
            float hold = h_s[jbase + tid];
            float hn   = (1.f - z) * c + z * hold;
            g_hs[(size_t)row * HID_ + jbase + tid] = tf32_rna(hn);
            uint32_t addr = h_base + (uint32_t)(jbase + tid) * 4u;
#pragma unroll
            for (int rk = 0; rk < 8; rk++) dsm_store(addr, rk, hn);
        }
        cluster_sync_();
    }
}

// ---------------- 4) output projection: R11-exact (128x128, occ 2, 2-stage) ----
#define ROWP    36
#define TILEF   (128 * ROWP)              // 4608 floats per operand tile
#define BUFF    (2 * TILEF)               // A + B, one stage (36864 B)
#define PROJ_SMEM (2 * BUFF * 4)          // 73728 bytes (2 CTAs/SM)

__global__ void __launch_bounds__(256, 2) gemm_mma(
    const float* __restrict__ A,   // g_hs  [8192,512], tf32 values
    const float* __restrict__ BT,  // g_WoT [32000,512], tf32 values
    const float* __restrict__ bias,
    float* __restrict__ C)
{
    extern __shared__ float sm[];
    uint32_t sbase = s2u(sm);
    int tid = threadIdx.x, lane = tid & 31, wid = tid >> 5;
    int wm = (wid >> 2) << 6;             // 0 / 64
    int wn = (wid & 3) << 5;              // 0 / 32 / 64 / 96
    size_t bm = (size_t)blockIdx.x * 128;
    size_t bn = (size_t)blockIdx.y * 128;

    float acc[4][4][4];
#pragma unroll
    for (int i = 0; i < 4; i++)
#pragma unroll
        for (int j = 0; j < 4; j++)
#pragma unroll
            for (int r = 0; r < 4; r++) acc[i][j][r] = 0.f;

    auto ISSUE = [&](int ch, int b) {
        uint32_t sa = sbase + (uint32_t)(b * BUFF) * 4u;
        uint32_t sb = sa + (uint32_t)TILEF * 4u;
#pragma unroll
        for (int p = 0; p < 4; p++) {
            int idx = tid + (p << 8);
            int row = idx >> 3, q = idx & 7;
            uint32_t so = (uint32_t)(row * ROWP + q * 4) * 4u;
            cp16(sa + so, A  + (bm + row) * HID_ + ch * 32 + q * 4);
            cp16(sb + so, BT + (bn + row) * HID_ + ch * 32 + q * 4);
        }
        asm volatile("cp.async.commit_group;" ::: "memory");
    };

    int r4 = lane >> 2, c4 = lane & 3;

    auto COMPUTE = [&](int b) {
        const float* pA = sm + b * BUFF;
        const float* pB = pA + TILEF;
#pragma unroll
        for (int ks = 0; ks < 4; ks++) {
            uint32_t af[4][4];
            uint32_t bf[4][2];
#pragma unroll
            for (int i = 0; i < 4; i++) {
                const float* base = pA + (wm + i * 16 + r4) * ROWP + ks * 8 + c4;
                af[i][0] = __float_as_uint(base[0]);
                af[i][1] = __float_as_uint(base[8 * ROWP]);
                af[i][2] = __float_as_uint(base[4]);
                af[i][3] = __float_as_uint(base[8 * ROWP + 4]);
            }
#pragma unroll
            for (int j = 0; j < 4; j++) {
                const float* base = pB + (wn + j * 8 + r4) * ROWP + ks * 8 + c4;
                bf[j][0] = __float_as_uint(base[0]);
                bf[j][1] = __float_as_uint(base[4]);
            }
#pragma unroll
            for (int i = 0; i < 4; i++)
#pragma unroll
                for (int j = 0; j < 4; j++)
                    asm volatile(
                        "mma.sync.aligned.m16n8k8.row.col.f32.tf32.tf32.f32 "
                        "{%0,%1,%2,%3}, {%4,%5,%6,%7}, {%8,%9}, {%0,%1,%2,%3};"
                        : "+f"(acc[i][j][0]), "+f"(acc[i][j][1]),
                          "+f"(acc[i][j][2]), "+f"(acc[i][j][3])
                        : "r"(af[i][0]), "r"(af[i][1]), "r"(af[i][2]), "r"(af[i][3]),
                          "r"(bf[j][0]), "r"(bf[j][1]));
        }
    };

    ISSUE(0, 0);
#pragma unroll 1
    for (int ch = 0; ch < 16; ch++) {
        if (ch < 15) {
            ISSUE(ch + 1, (ch + 1) & 1);
            asm volatile("cp.async.wait_group 1;" ::: "memory");
        } else {
            asm volatile("cp.async.wait_group 0;" ::: "memory");
        }
        __syncthreads();                  // chunk ch data visible to all warps
        COMPUTE(ch & 1);
        __syncthreads();                  // reads done before buffer re-issue
    }

    // epilogue
    float2 bv[4];
#pragma unroll
    for (int j = 0; j < 4; j++)
        bv[j] = __ldg((const float2*)(bias + bn + wn + (j << 3) + (c4 << 1)));

#pragma unroll
    for (int i = 0; i < 4; i++) {
        size_t row0 = bm + wm + (i << 4) + r4;
#pragma unroll
        for (int j = 0; j < 4; j++) {
            size_t col = bn + wn + (j << 3) + (c4 << 1);
            float2 v0 = make_float2(acc[i][j][0] + bv[j].x, acc[i][j][1] + bv[j].y);
            float2 v1 = make_float2(acc[i][j][2] + bv[j].x, acc[i][j][3] + bv[j].y);
            *(float2*)(C + row0 * VOCAB_ + col)       = v0;
            *(float2*)(C + (row0 + 8) * VOCAB_ + col) = v1;
        }
    }
}

// ---------------- launcher ----------------
extern "C" void kernel_launch(void* const* d_in, const int* in_sizes, int n_in,
                              void* d_out, int out_size) {
    const int*   tok   = (const int*)  d_in[0];
    const float* embed = (const float*)d_in[1];
    const float* Wr    = (const float*)d_in[2];
    const float* br    = (const float*)d_in[3];
    const float* Wz    = (const float*)d_in[4];
    const float* bz    = (const float*)d_in[5];
    const float* Wc    = (const float*)d_in[6];
    const float* bc    = (const float*)d_in[7];
    const float* Wo    = (const float*)d_in[8];
    const float* bo    = (const float*)d_in[9];
    float* out = (float*)d_out;

    float *xrp, *xzp, *xcp, *hsp, *wtp;
    cudaGetSymbolAddress((void**)&xrp, g_xr);
    cudaGetSymbolAddress((void**)&xzp, g_xz);
    cudaGetSymbolAddress((void**)&xcp, g_xc);
    cudaGetSymbolAddress((void**)&hsp, g_hs);
    cudaGetSymbolAddress((void**)&wtp, g_WoT);

    cudaFuncSetAttribute(gemm_mma, cudaFuncAttributeMaxDynamicSharedMemorySize,
                         PROJ_SMEM);

    cudaStream_t s2;
    cudaStreamCreate(&s2);
    cudaEvent_t evRoot, evT;
    cudaEventCreateWithFlags(&evRoot, cudaEventDisableTiming);
    cudaEventCreateWithFlags(&evT,    cudaEventDisableTiming);

    // fork FROM the capture stream (side stream must first wait on an event
    // recorded on stream 0 to join the capture graph — R13 lesson).
    cudaEventRecord(evRoot, 0);
    cudaStreamWaitEvent(s2, evRoot, 0);
    transpose_wo<<<dim3(VOCAB_ / 32, HID_ / 32), dim3(32, 8), 0, s2>>>(Wo);
    cudaEventRecord(evT, s2);

    // main stream: fused gather+x-projections -> GRU
    gemm_f32x3<<<dim3(HID_ / 128, NTOK / 128, 3), 256>>>(
        tok, embed,
        Wr + (size_t)HID_ * HID_, Wz + (size_t)HID_ * HID_, Wc + (size_t)HID_ * HID_,
        br, bz, bc, xrp, xzp, xcp);
    gru_kernel<<<64, 512>>>(Wr, Wz, Wc);

    // join transpose before the projection consumes g_WoT
    cudaStreamWaitEvent(0, evT, 0);
    gemm_mma<<<dim3(NTOK / 128, VOCAB_ / 128), 256, PROJ_SMEM>>>(hsp, wtp, bo, out);

    cudaEventDestroy(evRoot);
    cudaEventDestroy(evT);
    cudaStreamDestroy(s2);
}

// round 17
// speedup vs baseline: 1.1572x; 1.1487x over previous
#include <cuda_runtime.h>
#include <math.h>
#include <stdint.h>

#define B_     8
#define S_     1024
#define VOCAB_ 32000
#define EMBED_ 256
#define HID_   512
#define NTOK   (B_ * S_)

// ---------------- scratch (static device arrays; no allocation) ----------------
__device__ float g_X  [NTOK * EMBED_];
__device__ float g_xr [NTOK * HID_];
__device__ float g_xz [NTOK * HID_];
__device__ float g_xc [NTOK * HID_];
__device__ float g_hs [NTOK * HID_];     // tf32-rounded hidden states
__device__ float g_WoT[VOCAB_ * HID_];   // Wo transposed [N,K], tf32-rounded

// ---------------- helpers ----------------
__device__ __forceinline__ uint32_t s2u(const void* p) {
    return (uint32_t)__cvta_generic_to_shared(p);
}
__device__ __forceinline__ float tf32_rna(float x) {
    uint32_t u;
    asm("cvt.rna.tf32.f32 %0, %1;" : "=r"(u) : "f"(x));
    return __uint_as_float(u);
}
__device__ __forceinline__ void cluster_sync_() {
    asm volatile("barrier.cluster.arrive.aligned;" ::: "memory");
    asm volatile("barrier.cluster.wait.aligned;"   ::: "memory");
}
__device__ __forceinline__ void dsm_store(uint32_t saddr, int rank, float v) {
    uint32_t ra;
    asm volatile("mapa.shared::cluster.u32 %0, %1, %2;" : "=r"(ra) : "r"(saddr), "r"(rank));
    asm volatile("st.shared::cluster.f32 [%0], %1;" :: "r"(ra), "f"(v) : "memory");
}
__device__ __forceinline__ void cp16(uint32_t saddr, const void* g) {
    asm volatile("cp.async.cg.shared.global [%0], [%1], 16;"
                 :: "r"(saddr), "l"(g) : "memory");
}

// ---------------- 1) embedding gather ----------------
__global__ void gather_kernel(const int* __restrict__ tok,
                              const float* __restrict__ embed) {
    int t = blockIdx.x;
    int e = threadIdx.x << 2;
    int v = __ldg(tok + t);
    float4 val = *(const float4*)(embed + (size_t)v * EMBED_ + e);
    *(float4*)(g_X + (size_t)t * EMBED_ + e) = val;
}

// ---------------- 1b) Wo transpose + tf32 round: g_WoT[n][k] = rna(Wo[k][n]) ----------------
__global__ void transpose_wo(const float* __restrict__ Wo) {
    __shared__ float tile[32][33];
    int n0 = blockIdx.x * 32, k0 = blockIdx.y * 32;
    int tx = threadIdx.x, ty = threadIdx.y;   // 32 x 8
#pragma unroll
    for (int i = 0; i < 4; i++)
        tile[ty + i * 8][tx] = Wo[(size_t)(k0 + ty + i * 8) * VOCAB_ + n0 + tx];
    __syncthreads();
#pragma unroll
    for (int i = 0; i < 4; i++)
        g_WoT[(size_t)(n0 + ty + i * 8) * HID_ + k0 + tx] = tf32_rna(tile[tx][ty + i * 8]);
}

// ---------------- 2) fp32 tiled GEMM: all 3 x-projections in one launch ----------------
__global__ void __launch_bounds__(256, 2) gemm_f32x3(
    const float* __restrict__ A,
    const float* __restrict__ W0, const float* __restrict__ W1, const float* __restrict__ W2,
    const float* __restrict__ b0, const float* __restrict__ b1, const float* __restrict__ b2,
    float* __restrict__ C0, float* __restrict__ C1, float* __restrict__ C2)
{
    const int BM = 128, BN = 128, BK = 32;
    const int N = HID_, K = EMBED_;
    __shared__ float As[BK][BM + 4];
    __shared__ float Bs[BK][BN];

    const float* Bg  = (blockIdx.z == 0) ? W0 : (blockIdx.z == 1) ? W1 : W2;
    const float* bia = (blockIdx.z == 0) ? b0 : (blockIdx.z == 1) ? b1 : b2;
    float*       C   = (blockIdx.z == 0) ? C0 : (blockIdx.z == 1) ? C1 : C2;

    int tid = threadIdx.x;
    int bm = blockIdx.y * BM;
    int bn = blockIdx.x * BN;
    int tx = tid & 15;
    int ty = tid >> 4;

    float acc[8][8];
#pragma unroll
    for (int i = 0; i < 8; i++)
#pragma unroll
        for (int j = 0; j < 8; j++) acc[i][j] = 0.f;

    int arow = tid >> 3;
    int acol = (tid & 7) << 2;
    int brow = tid >> 5;
    int bcol = (tid & 31) << 2;

    for (int k0 = 0; k0 < K; k0 += BK) {
#pragma unroll
        for (int p = 0; p < 4; p++) {
            int r = arow + p * 32;
            float4 v = *(const float4*)(A + (size_t)(bm + r) * K + k0 + acol);
            As[acol + 0][r] = v.x; As[acol + 1][r] = v.y;
            As[acol + 2][r] = v.z; As[acol + 3][r] = v.w;
        }
#pragma unroll
        for (int p = 0; p < 4; p++) {
            int r = brow + p * 8;
            *(float4*)(&Bs[r][bcol]) =
                *(const float4*)(Bg + (size_t)(k0 + r) * N + bn + bcol);
        }
        __syncthreads();

#pragma unroll
        for (int kk = 0; kk < BK; kk++) {
            float a[8], b[8];
            *(float4*)(a)     = *(const float4*)(&As[kk][ty * 4]);
            *(float4*)(a + 4) = *(const float4*)(&As[kk][64 + ty * 4]);
            *(float4*)(b)     = *(const float4*)(&Bs[kk][tx * 4]);
            *(float4*)(b + 4) = *(const float4*)(&Bs[kk][64 + tx * 4]);
#pragma unroll
            for (int i = 0; i < 8; i++)
#pragma unroll
                for (int j = 0; j < 8; j++)
                    acc[i][j] = fmaf(a[i], b[j], acc[i][j]);
        }
        __syncthreads();
    }

    float4 bv0 = *(const float4*)(bia + bn + tx * 4);
    float4 bv1 = *(const float4*)(bia + bn + 64 + tx * 4);
#pragma unroll
    for (int i = 0; i < 8; i++) {
        int row = bm + ((i < 4) ? (ty * 4 + i) : (64 + ty * 4 + (i - 4)));
        float4 o0, o1;
        o0.x = acc[i][0] + bv0.x; o0.y = acc[i][1] + bv0.y;
        o0.z = acc[i][2] + bv0.z; o0.w = acc[i][3] + bv0.w;
        o1.x = acc[i][4] + bv1.x; o1.y = acc[i][5] + bv1.y;
        o1.z = acc[i][6] + bv1.z; o1.w = acc[i][7] + bv1.w;
        *(float4*)(C + (size_t)row * N + bn + tx * 4)      = o0;
        *(float4*)(C + (size_t)row * N + bn + 64 + tx * 4) = o1;
    }
}

// ---------------- 3) GRU recurrence: 8-CTA cluster, KC1=20, phase-2 W in smem ----
#define KC1 20
#define W2SMEM (HID_ * 64 * 4)            // 131072 bytes dynamic smem

__global__ void __launch_bounds__(512, 1) __cluster_dims__(8, 1, 1)
gru_kernel(const float* __restrict__ Wr, const float* __restrict__ Wz,
           const float* __restrict__ Wc)
{
    extern __shared__ float w2s[];        // [512][64]: phase-2 weight slice
    __shared__ float  h_s [HID_];
    __shared__ float  rh_s[HID_];
    __shared__ float  z_s [64];
    __shared__ float4 part[512];

    int tid   = threadIdx.x;
    int batch = blockIdx.x >> 3;
    int jbase = (blockIdx.x & 7) << 6;

    uint32_t rh_base = s2u(rh_s);
    uint32_t h_base  = s2u(h_s);

    // one-time: stage this CTA's phase-2 weight slice Wc[k][jbase..jbase+63]
    // layout w2s[k*64 + jl]; coalesced 256B runs per 16 lanes
#pragma unroll
    for (int p = 0; p < 16; p++) {
        int g = tid + (p << 9);           // granule id 0..8191
        int k = g >> 4, q = g & 15;
        *(float4*)(w2s + k * 64 + q * 4) =
            *(const float4*)(Wc + (size_t)k * HID_ + jbase + q * 4);
    }

    h_s[tid] = 0.f;
    __syncthreads();
    cluster_sync_();

    int g1  = tid >> 8;
    int jq1 = tid & 15;
    int kp1 = (tid >> 4) & 15;
    const float* W1 = g1 ? Wz : Wr;
    const float4* w1base =
        (const float4*)(W1 + (size_t)(kp1 * 32) * HID_ + jbase + jq1 * 4);

    int jq2 = tid & 15;
    int kp2 = tid >> 4;

    float4 wc[KC1];
#pragma unroll
    for (int i = 0; i < KC1; i++) wc[i] = __ldg(w1base + i * (HID_ / 4));
    const float4* w1rest = w1base + KC1 * (HID_ / 4);

    for (int t = 0; t < S_; t++) {
        int row = (batch << 10) + t;

        float xpre1 = 0.f;
        if (tid < 128) {
            int g2 = tid >> 6, jl = tid & 63;
            const float* xg = g2 ? g_xz : g_xr;
            xpre1 = __ldg(xg + (size_t)row * HID_ + jbase + jl);
        }

        // ---- phase 1: r and z pre-activations (h @ W_h) ----
        {
            float4 acc = make_float4(0.f, 0.f, 0.f, 0.f);
            int kb = kp1 * 32;
#pragma unroll
            for (int i = 0; i < KC1; i++) {
                float hv = h_s[kb + i];
                acc.x = fmaf(hv, wc[i].x, acc.x); acc.y = fmaf(hv, wc[i].y, acc.y);
                acc.z = fmaf(hv, wc[i].z, acc.z); acc.w = fmaf(hv, wc[i].w, acc.w);
            }
            const float4* wp = w1rest;
#pragma unroll
            for (int i = KC1; i < 32; i++) {
                float hv = h_s[kb + i];
                float4 w = __ldg(wp);
                acc.x = fmaf(hv, w.x, acc.x); acc.y = fmaf(hv, w.y, acc.y);
                acc.z = fmaf(hv, w.z, acc.z); acc.w = fmaf(hv, w.w, acc.w);
                wp += HID_ / 4;
            }
            part[(g1 << 8) + (kp1 << 4) + jq1] = acc;
        }
        __syncthreads();

        if (tid < 128) {
            int g2 = tid >> 6, jl = tid & 63;
            int jq = jl >> 2, comp = jl & 3;
            float sum = xpre1;
            const float* pf = (const float*)part + (g2 << 10) + (jq << 2) + comp;
#pragma unroll
            for (int kp = 0; kp < 16; kp++) sum += pf[kp * 64];
            float s = 1.f / (1.f + expf(-sum));
            if (g2 == 0) {
                float rh = s * h_s[jbase + jl];
                uint32_t addr = rh_base + (uint32_t)(jbase + jl) * 4u;
#pragma unroll
                for (int rk = 0; rk < 8; rk++) dsm_store(addr, rk, rh);
            } else {
                z_s[jl] = s;
            }
        }
        cluster_sync_();

        float xpre2 = 0.f;
        if (tid < 64)
            xpre2 = __ldg(g_xc + (size_t)row * HID_ + jbase + tid);

        // ---- phase 2: candidate c, h update (weights from smem) ----
        {
            float4 acc = make_float4(0.f, 0.f, 0.f, 0.f);
            int kb = kp2 * 16;
            const float* wp = w2s + kb * 64 + jq2 * 4;
#pragma unroll 8
            for (int i = 0; i < 16; i++) {
                float rv = rh_s[kb + i];
                float4 w = *(const float4*)(wp + i * 64);
                acc.x = fmaf(rv, w.x, acc.x); acc.y = fmaf(rv, w.y, acc.y);
                acc.z = fmaf(rv, w.z, acc.z); acc.w = fmaf(rv, w.w, acc.w);
            }
            part[(kp2 << 4) + jq2] = acc;
        }
        __syncthreads();

        if (tid < 64) {
            int jq = tid >> 2, comp = tid & 3;
            float sum = xpre2;
            const float* pf = (const float*)part + (jq << 2) + comp;
#pragma unroll
            for (int kp = 0; kp < 32; kp++) sum += pf[kp * 64];
            float c    = tanhf(sum);
            float z    = z_s[tid];
            float hold = h_s[jbase + tid];
            float hn   = (1.f - z) * c + z * hold;
            g_hs[(size_t)row * HID_ + jbase + tid] = tf32_rna(hn);
            uint32_t addr = h_base + (uint32_t)(jbase + tid) * 4u;
#pragma unroll
            for (int rk = 0; rk < 8; rk++) dsm_store(addr, rk, hn);
        }
        cluster_sync_();
    }
}

// ---------------- 4) output projection: R11-exact (128x128, occ 2, 2-stage) ----
#define ROWP    36
#define TILEF   (128 * ROWP)              // 4608 floats per operand tile
#define BUFF    (2 * TILEF)               // A + B, one stage (36864 B)
#define PROJ_SMEM (2 * BUFF * 4)          // 73728 bytes (2 CTAs/SM)

__global__ void __launch_bounds__(256, 2) gemm_mma(
    const float* __restrict__ A,   // g_hs  [8192,512], tf32 values
    const float* __restrict__ BT,  // g_WoT [32000,512], tf32 values
    const float* __restrict__ bias,
    float* __restrict__ C)
{
    extern __shared__ float sm[];
    uint32_t sbase = s2u(sm);
    int tid = threadIdx.x, lane = tid & 31, wid = tid >> 5;
    int wm = (wid >> 2) << 6;             // 0 / 64
    int wn = (wid & 3) << 5;              // 0 / 32 / 64 / 96
    size_t bm = (size_t)blockIdx.x * 128;
    size_t bn = (size_t)blockIdx.y * 128;

    float acc[4][4][4];
#pragma unroll
    for (int i = 0; i < 4; i++)
#pragma unroll
        for (int j = 0; j < 4; j++)
#pragma unroll
            for (int r = 0; r < 4; r++) acc[i][j][r] = 0.f;

    auto ISSUE = [&](int ch, int b) {
        uint32_t sa = sbase + (uint32_t)(b * BUFF) * 4u;
        uint32_t sb = sa + (uint32_t)TILEF * 4u;
#pragma unroll
        for (int p = 0; p < 4; p++) {
            int idx = tid + (p << 8);
            int row = idx >> 3, q = idx & 7;
            uint32_t so = (uint32_t)(row * ROWP + q * 4) * 4u;
            cp16(sa + so, A  + (bm + row) * HID_ + ch * 32 + q * 4);
            cp16(sb + so, BT + (bn + row) * HID_ + ch * 32 + q * 4);
        }
        asm volatile("cp.async.commit_group;" ::: "memory");
    };

    int r4 = lane >> 2, c4 = lane & 3;

    auto COMPUTE = [&](int b) {
        const float* pA = sm + b * BUFF;
        const float* pB = pA + TILEF;
#pragma unroll
        for (int ks = 0; ks < 4; ks++) {
            uint32_t af[4][4];
            uint32_t bf[4][2];
#pragma unroll
            for (int i = 0; i < 4; i++) {
                const float* base = pA + (wm + i * 16 + r4) * ROWP + ks * 8 + c4;
                af[i][0] = __float_as_uint(base[0]);
                af[i][1] = __float_as_uint(base[8 * ROWP]);
                af[i][2] = __float_as_uint(base[4]);
                af[i][3] = __float_as_uint(base[8 * ROWP + 4]);
            }
#pragma unroll
            for (int j = 0; j < 4; j++) {
                const float* base = pB + (wn + j * 8 + r4) * ROWP + ks * 8 + c4;
                bf[j][0] = __float_as_uint(base[0]);
                bf[j][1] = __float_as_uint(base[4]);
            }
#pragma unroll
            for (int i = 0; i < 4; i++)
#pragma unroll
                for (int j = 0; j < 4; j++)
                    asm volatile(
                        "mma.sync.aligned.m16n8k8.row.col.f32.tf32.tf32.f32 "
                        "{%0,%1,%2,%3}, {%4,%5,%6,%7}, {%8,%9}, {%0,%1,%2,%3};"
                        : "+f"(acc[i][j][0]), "+f"(acc[i][j][1]),
                          "+f"(acc[i][j][2]), "+f"(acc[i][j][3])
                        : "r"(af[i][0]), "r"(af[i][1]), "r"(af[i][2]), "r"(af[i][3]),
                          "r"(bf[j][0]), "r"(bf[j][1]));
        }
    };

    ISSUE(0, 0);
#pragma unroll 1
    for (int ch = 0; ch < 16; ch++) {
        if (ch < 15) {
            ISSUE(ch + 1, (ch + 1) & 1);
            asm volatile("cp.async.wait_group 1;" ::: "memory");
        } else {
            asm volatile("cp.async.wait_group 0;" ::: "memory");
        }
        __syncthreads();                  // chunk ch data visible to all warps
        COMPUTE(ch & 1);
        __syncthreads();                  // reads done before buffer re-issue
    }

    // epilogue
    float2 bv[4];
#pragma unroll
    for (int j = 0; j < 4; j++)
        bv[j] = __ldg((const float2*)(bias + bn + wn + (j << 3) + (c4 << 1)));

#pragma unroll
    for (int i = 0; i < 4; i++) {
        size_t row0 = bm + wm + (i << 4) + r4;
#pragma unroll
        for (int j = 0; j < 4; j++) {
            size_t col = bn + wn + (j << 3) + (c4 << 1);
            float2 v0 = make_float2(acc[i][j][0] + bv[j].x, acc[i][j][1] + bv[j].y);
            float2 v1 = make_float2(acc[i][j][2] + bv[j].x, acc[i][j][3] + bv[j].y);
            *(float2*)(C + row0 * VOCAB_ + col)       = v0;
            *(float2*)(C + (row0 + 8) * VOCAB_ + col) = v1;
        }
    }
}

// ---------------- launcher (sequential, single stream — nothing co-runs w/ GRU) ----
extern "C" void kernel_launch(void* const* d_in, const int* in_sizes, int n_in,
                              void* d_out, int out_size) {
    const int*   tok   = (const int*)  d_in[0];
    const float* embed = (const float*)d_in[1];
    const float* Wr    = (const float*)d_in[2];
    const float* br    = (const float*)d_in[3];
    const float* Wz    = (const float*)d_in[4];
    const float* bz    = (const float*)d_in[5];
    const float* Wc    = (const float*)d_in[6];
    const float* bc    = (const float*)d_in[7];
    const float* Wo    = (const float*)d_in[8];
    const float* bo    = (const float*)d_in[9];
    float* out = (float*)d_out;

    float *xp, *xrp, *xzp, *xcp, *hsp, *wtp;
    cudaGetSymbolAddress((void**)&xp,  g_X);
    cudaGetSymbolAddress((void**)&xrp, g_xr);
    cudaGetSymbolAddress((void**)&xzp, g_xz);
    cudaGetSymbolAddress((void**)&xcp, g_xc);
    cudaGetSymbolAddress((void**)&hsp, g_hs);
    cudaGetSymbolAddress((void**)&wtp, g_WoT);

    cudaFuncSetAttribute(gemm_mma, cudaFuncAttributeMaxDynamicSharedMemorySize,
                         PROJ_SMEM);
    cudaFuncSetAttribute(gru_kernel, cudaFuncAttributeMaxDynamicSharedMemorySize,
                         W2SMEM);

    // 1) gather + Wo transpose (serial; R15 proved co-running hurts)
    gather_kernel<<<NTOK, 64>>>(tok, embed);
    transpose_wo<<<dim3(VOCAB_ / 32, HID_ / 32), dim3(32, 8)>>>(Wo);

    // 2) x-dependent gate inputs (+bias): rows 512..767 of each W (one launch)
    gemm_f32x3<<<dim3(HID_ / 128, NTOK / 128, 3), 256>>>(
        xp,
        Wr + (size_t)HID_ * HID_, Wz + (size_t)HID_ * HID_, Wc + (size_t)HID_ * HID_,
        br, bz, bc, xrp, xzp, xcp);

    // 3) sequential GRU scan (phase-2 weights smem-resident)
    gru_kernel<<<64, 512, W2SMEM>>>(Wr, Wz, Wc);

    // 4) output projection on tensor cores (mma.sync tf32)
    gemm_mma<<<dim3(NTOK / 128, VOCAB_ / 128), 256, PROJ_SMEM>>>(hsp, wtp, bo, out);
}